// round 4
// baseline (speedup 1.0000x reference)
#include <cuda_runtime.h>
#include <math.h>

#define NN 50000
#define FF 128

// ---------------- scratch (device globals; no allocation) ----------------
// xt1: [N][4][16]  slots 0..14 = W_r x, slot 15 = (W_r x)·k1  (ak packed)
__device__ __align__(16) float d_xt1[NN * 64];
__device__ float d_aq1[NN * 4];
// agg1: [N][16]  slots 0..14 = weighted msg sum, slot 15 = softmax denom
__device__ __align__(16) float d_agg1[NN * 16];
__device__ float d_h1[NN * 16];
// xt2: [N][4][16] slots 0..9 vals, slot 10 = ak2, 11..15 pad
__device__ __align__(16) float d_xt2[NN * 64];
__device__ float d_aq2[NN * 4];
// agg2: [N][12] slots 0..9 vals, 10 denom, 11 pad
__device__ __align__(16) float d_agg2[NN * 12];
__device__ float d_h2[NN * 10];
__device__ float d_CW1[128 * 68];   // cols 0..59 = W1, 60..63 = W1@q1, 64..67 = W1@k1
__device__ float d_CW2[15 * 48];    // cols 0..39 = W2, 40..43 = W2@q2, 44..47 = W2@k2
__device__ float d_stats[64];
__device__ float d_bn1s[15], d_bn1b[15], d_bn2s[10], d_bn2b[10];
__device__ float d_c1, d_c2;

// ---------------- helpers ----------------
__device__ __forceinline__ void red4(float* p, float a, float b, float c, float d) {
    asm volatile("red.global.add.v4.f32 [%0], {%1,%2,%3,%4};"
                 :: "l"(p), "f"(a), "f"(b), "f"(c), "f"(d) : "memory");
}

// ---------------- init ----------------
__global__ void k_zero() {
    const int tot = NN * 16 + NN * 12 + 64;
    for (int i = blockIdx.x * blockDim.x + threadIdx.x; i < tot; i += gridDim.x * blockDim.x) {
        if (i < NN * 16)            d_agg1[i] = 0.f;
        else if (i < NN * 28)       d_agg2[i - NN * 16] = 0.f;
        else                        d_stats[i - NN * 28] = 0.f;
    }
}

// ---------------- weight prep ----------------
__global__ void k_build1(const float* __restrict__ W1, const float* __restrict__ q1,
                         const float* __restrict__ k1) {
    int i = blockIdx.x * 256 + threadIdx.x;
    if (i >= 128 * 68) return;
    int f = i / 68, c = i % 68;
    float v;
    if (c < 60) {
        int r = c / 15, o = c % 15;
        v = W1[(r * 128 + f) * 15 + o];
    } else if (c < 64) {
        int r = c - 60; float s = 0.f;
        for (int o = 0; o < 15; ++o) s += W1[(r * 128 + f) * 15 + o] * q1[o];
        v = s;
    } else {
        int r = c - 64; float s = 0.f;
        for (int o = 0; o < 15; ++o) s += W1[(r * 128 + f) * 15 + o] * k1[o];
        v = s;
    }
    d_CW1[i] = v;
}

__global__ void k_build2(const float* __restrict__ W2, const float* __restrict__ q2,
                         const float* __restrict__ k2,
                         const float* __restrict__ We1, const float* __restrict__ e1,
                         const float* __restrict__ We2, const float* __restrict__ e2) {
    int i = blockIdx.x * 256 + threadIdx.x;
    if (i == 0) {
        float s = 0.f;
        for (int o = 0; o < 15; ++o) s += We1[o] * e1[o];
        d_c1 = s;
        float t = 0.f;
        for (int o = 0; o < 10; ++o) t += We2[o] * e2[o];
        d_c2 = t;
    }
    if (i >= 15 * 48) return;
    int f = i / 48, c = i % 48;
    float v;
    if (c < 40) {
        int r = c / 10, o = c % 10;
        v = W2[(r * 15 + f) * 10 + o];
    } else if (c < 44) {
        int r = c - 40; float s = 0.f;
        for (int o = 0; o < 10; ++o) s += W2[(r * 15 + f) * 10 + o] * q2[o];
        v = s;
    } else {
        int r = c - 44; float s = 0.f;
        for (int o = 0; o < 10; ++o) s += W2[(r * 15 + f) * 10 + o] * k2[o];
        v = s;
    }
    d_CW2[i] = v;
}

// ---------------- layer-1 GEMM: [N,128] @ [128,68] ----------------
// 128 threads = 32 node-groups x 4 col-groups; thread owns 4 nodes x 17 cols.
// 128 nodes/block -> grid ~391, 4 blocks/SM (regs 13.8K, smem 25.6KB).
__global__ void __launch_bounds__(128) k_gemm1(const float* __restrict__ x, int n_nodes) {
    __shared__ float xs[128 * 33];   // 128 nodes x 32 f (padded 33)
    __shared__ float ws[32 * 68];
    const int tid = threadIdx.x;
    const int nbase = blockIdx.x * 128;
    const int ng = tid >> 2, cg = tid & 3;

    float acc[4][17];
#pragma unroll
    for (int i = 0; i < 4; ++i)
#pragma unroll
        for (int c = 0; c < 17; ++c) acc[i][c] = 0.f;

    const bool full = (nbase + 128 <= n_nodes);

    for (int ft = 0; ft < 4; ++ft) {
        // load x tile: 128 nodes x 32 f via float4 (8 quads per node)
#pragma unroll
        for (int k = 0; k < 8; ++k) {
            int idx = k * 128 + tid;          // 0..1023
            int nl = idx >> 3, q = idx & 7;   // node-local, quad
            int n = nbase + nl;
            float4 v = make_float4(0.f, 0.f, 0.f, 0.f);
            if (full || n < n_nodes)
                v = *reinterpret_cast<const float4*>(x + (size_t)n * FF + ft * 32 + q * 4);
            xs[nl * 33 + q * 4 + 0] = v.x;
            xs[nl * 33 + q * 4 + 1] = v.y;
            xs[nl * 33 + q * 4 + 2] = v.z;
            xs[nl * 33 + q * 4 + 3] = v.w;
        }
        for (int i = tid; i < 32 * 68; i += 128) ws[i] = d_CW1[ft * 32 * 68 + i];
        __syncthreads();
#pragma unroll 4
        for (int f = 0; f < 32; ++f) {
            float x0 = xs[(ng * 4 + 0) * 33 + f];
            float x1 = xs[(ng * 4 + 1) * 33 + f];
            float x2 = xs[(ng * 4 + 2) * 33 + f];
            float x3 = xs[(ng * 4 + 3) * 33 + f];
#pragma unroll
            for (int c = 0; c < 17; ++c) {
                float w = ws[f * 68 + cg * 17 + c];
                acc[0][c] += x0 * w;
                acc[1][c] += x1 * w;
                acc[2][c] += x2 * w;
                acc[3][c] += x3 * w;
            }
        }
        __syncthreads();
    }

#pragma unroll
    for (int i = 0; i < 4; ++i) {
        int n = nbase + ng * 4 + i;
        if (n >= n_nodes) break;
#pragma unroll
        for (int c = 0; c < 17; ++c) {
            int col = cg * 17 + c;
            float v = acc[i][c];
            if (col < 60)      d_xt1[n * 64 + (col / 15) * 16 + (col % 15)] = v;
            else if (col < 64) d_aq1[n * 4 + col - 60] = v;
            else               d_xt1[n * 64 + (col - 64) * 16 + 15] = v;   // ak packed
        }
    }
}

// ---------------- edge pass 1 ----------------
__global__ void __launch_bounds__(256) k_edge1(const int* __restrict__ ei, const int* __restrict__ et,
                                               const float* __restrict__ ea, int ne) {
    int e = blockIdx.x * 256 + threadIdx.x;
    if (e >= ne) return;
    int s = ei[e], d = ei[ne + e];
    int r = et[e];
    const float4* xp = reinterpret_cast<const float4*>(d_xt1 + ((size_t)s * 4 + r) * 16);
    float4 v0 = xp[0], v1 = xp[1], v2 = xp[2], v3 = xp[3];   // v3.w = ak[s,r]
    float a = d_aq1[d * 4 + r] + v3.w + ea[e] * d_c1;
    a = (a > 0.f) ? a : 0.2f * a;
    float ex = __expf(a);
    float* ag = d_agg1 + (size_t)d * 16;
    red4(ag + 0,  ex * v0.x, ex * v0.y, ex * v0.z, ex * v0.w);
    red4(ag + 4,  ex * v1.x, ex * v1.y, ex * v1.z, ex * v1.w);
    red4(ag + 8,  ex * v2.x, ex * v2.y, ex * v2.z, ex * v2.w);
    red4(ag + 12, ex * v3.x, ex * v3.y, ex * v3.z, ex);      // .w accumulates denom
}

// ---------------- post layer 1: normalize + bias, BN stats ----------------
__global__ void __launch_bounds__(256) k_post1(const float* __restrict__ b1, int n_nodes) {
    int n = blockIdx.x * 256 + threadIdx.x;
    float h[15];
#pragma unroll
    for (int o = 0; o < 15; ++o) h[o] = 0.f;
    if (n < n_nodes) {
        float inv = 1.f / (d_agg1[n * 16 + 15] + 1e-16f);
#pragma unroll
        for (int o = 0; o < 15; ++o) {
            h[o] = d_agg1[n * 16 + o] * inv + b1[o];
            d_h1[n * 16 + o] = h[o];
        }
    }
    __shared__ float ssum[15], ssq[15];
    if (threadIdx.x < 15) { ssum[threadIdx.x] = 0.f; ssq[threadIdx.x] = 0.f; }
    __syncthreads();
#pragma unroll
    for (int o = 0; o < 15; ++o) {
        float s = h[o], s2 = h[o] * h[o];
        for (int off = 16; off; off >>= 1) {
            s  += __shfl_down_sync(0xffffffffu, s, off);
            s2 += __shfl_down_sync(0xffffffffu, s2, off);
        }
        if ((threadIdx.x & 31) == 0) { atomicAdd(&ssum[o], s); atomicAdd(&ssq[o], s2); }
    }
    __syncthreads();
    if (threadIdx.x < 15)                               atomicAdd(&d_stats[threadIdx.x], ssum[threadIdx.x]);
    else if (threadIdx.x >= 16 && threadIdx.x < 31)     atomicAdd(&d_stats[threadIdx.x], ssq[threadIdx.x - 16]);
}

__global__ void k_bnfin1(const float* __restrict__ g, const float* __restrict__ beta, int n_nodes) {
    int o = threadIdx.x;
    if (o < 15) {
        float invn = 1.f / (float)n_nodes;
        float mean = d_stats[o] * invn;
        float var  = d_stats[16 + o] * invn - mean * mean;
        float sc = g[o] * rsqrtf(var + 1e-5f);
        d_bn1s[o] = sc;
        d_bn1b[o] = beta[o] - mean * sc;
    }
}

// ---------------- layer-2: BN+ELU then [N,15] @ [15,48] ----------------
__global__ void __launch_bounds__(256) k_gemm2(int n_nodes) {
    __shared__ float w2s[720];
    for (int i = threadIdx.x; i < 720; i += 256) w2s[i] = d_CW2[i];
    __syncthreads();
    int n = blockIdx.x * 256 + threadIdx.x;
    if (n >= n_nodes) return;
    float x2[15];
#pragma unroll
    for (int o = 0; o < 15; ++o) {
        float v = d_h1[n * 16 + o] * d_bn1s[o] + d_bn1b[o];
        x2[o] = (v > 0.f) ? v : expm1f(v);
    }
    float outv[48];
#pragma unroll
    for (int c = 0; c < 48; ++c) {
        float s = 0.f;
#pragma unroll
        for (int i = 0; i < 15; ++i) s += x2[i] * w2s[i * 48 + c];
        outv[c] = s;
    }
#pragma unroll
    for (int c = 0; c < 40; ++c) d_xt2[n * 64 + (c / 10) * 16 + (c % 10)] = outv[c];
#pragma unroll
    for (int r = 0; r < 4; ++r) {
        d_aq2[n * 4 + r] = outv[40 + r];
        d_xt2[n * 64 + r * 16 + 10] = outv[44 + r];   // ak2 packed
        d_xt2[n * 64 + r * 16 + 11] = 0.f;
    }
}

// ---------------- edge pass 2 ----------------
__global__ void __launch_bounds__(256) k_edge2(const int* __restrict__ ei, const int* __restrict__ et,
                                               const float* __restrict__ ea, int ne) {
    int e = blockIdx.x * 256 + threadIdx.x;
    if (e >= ne) return;
    int s = ei[e], d = ei[ne + e];
    int r = et[e];
    const float4* xp = reinterpret_cast<const float4*>(d_xt2 + ((size_t)s * 4 + r) * 16);
    float4 v0 = xp[0], v1 = xp[1], v2 = xp[2];   // v2.z = ak2[s,r]
    float a = d_aq2[d * 4 + r] + v2.z + ea[e] * d_c2;
    a = (a > 0.f) ? a : 0.2f * a;
    float ex = __expf(a);
    float* ag = d_agg2 + (size_t)d * 12;
    red4(ag + 0, ex * v0.x, ex * v0.y, ex * v0.z, ex * v0.w);
    red4(ag + 4, ex * v1.x, ex * v1.y, ex * v1.z, ex * v1.w);
    red4(ag + 8, ex * v2.x, ex * v2.y, ex, 0.f);             // slot10 = denom
}

// ---------------- post layer 2 ----------------
__global__ void __launch_bounds__(256) k_post2(const float* __restrict__ b2, int n_nodes) {
    int n = blockIdx.x * 256 + threadIdx.x;
    float h[10];
#pragma unroll
    for (int o = 0; o < 10; ++o) h[o] = 0.f;
    if (n < n_nodes) {
        float inv = 1.f / (d_agg2[n * 12 + 10] + 1e-16f);
#pragma unroll
        for (int o = 0; o < 10; ++o) {
            h[o] = d_agg2[n * 12 + o] * inv + b2[o];
            d_h2[n * 10 + o] = h[o];
        }
    }
    __shared__ float ssum[10], ssq[10];
    if (threadIdx.x < 10) { ssum[threadIdx.x] = 0.f; ssq[threadIdx.x] = 0.f; }
    __syncthreads();
#pragma unroll
    for (int o = 0; o < 10; ++o) {
        float s = h[o], s2 = h[o] * h[o];
        for (int off = 16; off; off >>= 1) {
            s  += __shfl_down_sync(0xffffffffu, s, off);
            s2 += __shfl_down_sync(0xffffffffu, s2, off);
        }
        if ((threadIdx.x & 31) == 0) { atomicAdd(&ssum[o], s); atomicAdd(&ssq[o], s2); }
    }
    __syncthreads();
    if (threadIdx.x < 10)                               atomicAdd(&d_stats[32 + threadIdx.x], ssum[threadIdx.x]);
    else if (threadIdx.x >= 16 && threadIdx.x < 26)     atomicAdd(&d_stats[48 + threadIdx.x - 16], ssq[threadIdx.x - 16]);
}

__global__ void k_bnfin2(const float* __restrict__ g, const float* __restrict__ beta, int n_nodes) {
    int o = threadIdx.x;
    if (o < 10) {
        float invn = 1.f / (float)n_nodes;
        float mean = d_stats[32 + o] * invn;
        float var  = d_stats[48 + o] * invn - mean * mean;
        float sc = g[o] * rsqrtf(var + 1e-5f);
        d_bn2s[o] = sc;
        d_bn2b[o] = beta[o] - mean * sc;
    }
}

// ---------------- head ----------------
__global__ void __launch_bounds__(256) k_head(const float* __restrict__ wh, const float* __restrict__ bh,
                                              float* __restrict__ out, int n_nodes) {
    int n = blockIdx.x * 256 + threadIdx.x;
    if (n >= n_nodes) return;
    float s = bh[0];
#pragma unroll
    for (int o = 0; o < 10; ++o) {
        float v = d_h2[n * 10 + o] * d_bn2s[o] + d_bn2b[o];
        v = (v > 0.f) ? v : expm1f(v);
        s += v * wh[o];
    }
    out[n] = s;
}

// ---------------- launch ----------------
extern "C" void kernel_launch(void* const* d_in, const int* in_sizes, int n_in,
                              void* d_out, int out_size) {
    const float* x   = (const float*)d_in[0];
    const int*   ei  = (const int*)  d_in[1];
    const int*   et  = (const int*)  d_in[2];
    const float* ea  = (const float*)d_in[3];
    const float* W1  = (const float*)d_in[4];
    const float* q1  = (const float*)d_in[5];
    const float* k1  = (const float*)d_in[6];
    const float* e1  = (const float*)d_in[7];
    const float* We1 = (const float*)d_in[8];
    const float* b1  = (const float*)d_in[9];
    const float* W2  = (const float*)d_in[10];
    const float* q2  = (const float*)d_in[11];
    const float* k2  = (const float*)d_in[12];
    const float* e2  = (const float*)d_in[13];
    const float* We2 = (const float*)d_in[14];
    const float* b2  = (const float*)d_in[15];
    const float* g1  = (const float*)d_in[16];
    const float* bt1 = (const float*)d_in[17];
    const float* g2  = (const float*)d_in[18];
    const float* bt2 = (const float*)d_in[19];
    const float* wh  = (const float*)d_in[20];
    const float* bh  = (const float*)d_in[21];
    float* out = (float*)d_out;

    int n  = in_sizes[0] / FF;
    int ne = in_sizes[1] / 2;

    k_zero<<<2048, 256>>>();
    k_build1<<<(128 * 68 + 255) / 256, 256>>>(W1, q1, k1);
    k_build2<<<3, 256>>>(W2, q2, k2, We1, e1, We2, e2);
    k_gemm1<<<(n + 127) / 128, 128>>>(x, n);
    k_edge1<<<(ne + 255) / 256, 256>>>(ei, et, ea, ne);
    k_post1<<<(n + 255) / 256, 256>>>(b1, n);
    k_bnfin1<<<1, 32>>>(g1, bt1, n);
    k_gemm2<<<(n + 255) / 256, 256>>>(n);
    k_edge2<<<(ne + 255) / 256, 256>>>(ei, et, ea, ne);
    k_post2<<<(n + 255) / 256, 256>>>(b2, n);
    k_bnfin2<<<1, 32>>>(g2, bt2, n);
    k_head<<<(n + 255) / 256, 256>>>(wh, bh, out, n);
}

// round 7
// speedup vs baseline: 1.4011x; 1.4011x over previous
#include <cuda_runtime.h>
#include <math.h>

#define NN 50000
#define FF 128

// ---------------- scratch (device globals; no allocation) ----------------
// xt1: [N][4][16]  slots 0..14 = W_r x, slot 15 = (W_r x)·k1  (ak packed)
__device__ __align__(16) float d_xt1[NN * 64];
__device__ float d_aq1[NN * 4];
// agg1: [N][16]  slots 0..14 = weighted msg sum, slot 15 = softmax denom
__device__ __align__(16) float d_agg1[NN * 16];
__device__ float d_h1[NN * 16];
// xt2: [N][4][16] slots 0..9 vals, slot 10 = ak2, 11..15 pad
__device__ __align__(16) float d_xt2[NN * 64];
__device__ float d_aq2[NN * 4];
// agg2: [N][12] slots 0..9 vals, 10 denom, 11 pad
__device__ __align__(16) float d_agg2[NN * 12];
__device__ float d_h2[NN * 10];
__device__ float d_CW1[128 * 68];   // cols 0..59 = W1, 60..63 = W1@q1, 64..67 = W1@k1
__device__ float d_CW2[15 * 48];    // cols 0..39 = W2, 40..43 = W2@q2, 44..47 = W2@k2
__device__ float d_stats[64];
__device__ float d_bn1s[15], d_bn1b[15], d_bn2s[10], d_bn2b[10];
__device__ float d_c1, d_c2;

// ---------------- helpers ----------------
__device__ __forceinline__ void red4(float* p, float a, float b, float c, float d) {
    asm volatile("red.global.add.v4.f32 [%0], {%1,%2,%3,%4};"
                 :: "l"(p), "f"(a), "f"(b), "f"(c), "f"(d) : "memory");
}

// ---------------- init ----------------
__global__ void k_zero() {
    const int tot = NN * 16 + NN * 12 + 64;
    for (int i = blockIdx.x * blockDim.x + threadIdx.x; i < tot; i += gridDim.x * blockDim.x) {
        if (i < NN * 16)            d_agg1[i] = 0.f;
        else if (i < NN * 28)       d_agg2[i - NN * 16] = 0.f;
        else                        d_stats[i - NN * 28] = 0.f;
    }
}

// ---------------- weight prep ----------------
__global__ void k_build1(const float* __restrict__ W1, const float* __restrict__ q1,
                         const float* __restrict__ k1) {
    int i = blockIdx.x * 256 + threadIdx.x;
    if (i >= 128 * 68) return;
    int f = i / 68, c = i % 68;
    float v;
    if (c < 60) {
        int r = c / 15, o = c % 15;
        v = W1[(r * 128 + f) * 15 + o];
    } else if (c < 64) {
        int r = c - 60; float s = 0.f;
        for (int o = 0; o < 15; ++o) s += W1[(r * 128 + f) * 15 + o] * q1[o];
        v = s;
    } else {
        int r = c - 64; float s = 0.f;
        for (int o = 0; o < 15; ++o) s += W1[(r * 128 + f) * 15 + o] * k1[o];
        v = s;
    }
    d_CW1[i] = v;
}

__global__ void k_build2(const float* __restrict__ W2, const float* __restrict__ q2,
                         const float* __restrict__ k2,
                         const float* __restrict__ We1, const float* __restrict__ e1,
                         const float* __restrict__ We2, const float* __restrict__ e2) {
    int i = blockIdx.x * 256 + threadIdx.x;
    if (i == 0) {
        float s = 0.f;
        for (int o = 0; o < 15; ++o) s += We1[o] * e1[o];
        d_c1 = s;
        float t = 0.f;
        for (int o = 0; o < 10; ++o) t += We2[o] * e2[o];
        d_c2 = t;
    }
    if (i >= 15 * 48) return;
    int f = i / 48, c = i % 48;
    float v;
    if (c < 40) {
        int r = c / 10, o = c % 10;
        v = W2[(r * 15 + f) * 10 + o];
    } else if (c < 44) {
        int r = c - 40; float s = 0.f;
        for (int o = 0; o < 10; ++o) s += W2[(r * 15 + f) * 10 + o] * q2[o];
        v = s;
    } else {
        int r = c - 44; float s = 0.f;
        for (int o = 0; o < 10; ++o) s += W2[(r * 15 + f) * 10 + o] * k2[o];
        v = s;
    }
    d_CW2[i] = v;
}

// ---------------- layer-1 GEMM: [N,128] @ [128,68] ----------------
// 256 threads = 64 nodes x 4 col-groups; thread owns 1 node x 17 cols.
// 64 nodes/block -> grid 782 -> ~5.3 blocks/SM x 8 warps = ~42 warps/SM.
__global__ void __launch_bounds__(256) k_gemm1(const float* __restrict__ x, int n_nodes) {
    __shared__ float xs[64 * 33];    // 64 nodes x 32 f (padded 33)
    __shared__ float ws[32 * 68];
    const int tid = threadIdx.x;
    const int nbase = blockIdx.x * 64;
    const int ng = tid >> 2, cg = tid & 3;   // node-local 0..63, col-group 0..3

    float acc[17];
#pragma unroll
    for (int c = 0; c < 17; ++c) acc[c] = 0.f;

    const bool full = (nbase + 64 <= n_nodes);

    for (int ft = 0; ft < 4; ++ft) {
        // load x tile: 64 nodes x 32 f = 512 float4s; 2 per thread
#pragma unroll
        for (int k = 0; k < 2; ++k) {
            int idx = k * 256 + tid;          // 0..511
            int nl = idx >> 3, q = idx & 7;   // node-local, quad
            int n = nbase + nl;
            float4 v = make_float4(0.f, 0.f, 0.f, 0.f);
            if (full || n < n_nodes)
                v = *reinterpret_cast<const float4*>(x + (size_t)n * FF + ft * 32 + q * 4);
            xs[nl * 33 + q * 4 + 0] = v.x;
            xs[nl * 33 + q * 4 + 1] = v.y;
            xs[nl * 33 + q * 4 + 2] = v.z;
            xs[nl * 33 + q * 4 + 3] = v.w;
        }
        for (int i = tid; i < 32 * 68; i += 256) ws[i] = d_CW1[ft * 32 * 68 + i];
        __syncthreads();
#pragma unroll
        for (int f = 0; f < 32; ++f) {
            float xv = xs[ng * 33 + f];
#pragma unroll
            for (int c = 0; c < 17; ++c)
                acc[c] += xv * ws[f * 68 + cg * 17 + c];
        }
        __syncthreads();
    }

    int n = nbase + ng;
    if (n < n_nodes) {
#pragma unroll
        for (int c = 0; c < 17; ++c) {
            int col = cg * 17 + c;
            float v = acc[c];
            if (col < 60)      d_xt1[n * 64 + (col / 15) * 16 + (col % 15)] = v;
            else if (col < 64) d_aq1[n * 4 + col - 60] = v;
            else               d_xt1[n * 64 + (col - 64) * 16 + 15] = v;   // ak packed
        }
    }
}

// ---------------- edge pass 1 ----------------
__global__ void __launch_bounds__(256) k_edge1(const int* __restrict__ ei, const int* __restrict__ et,
                                               const float* __restrict__ ea, int ne) {
    int e = blockIdx.x * 256 + threadIdx.x;
    if (e >= ne) return;
    int s = ei[e], d = ei[ne + e];
    int r = et[e];
    const float4* xp = reinterpret_cast<const float4*>(d_xt1 + ((size_t)s * 4 + r) * 16);
    float4 v0 = xp[0], v1 = xp[1], v2 = xp[2], v3 = xp[3];   // v3.w = ak[s,r]
    float a = d_aq1[d * 4 + r] + v3.w + ea[e] * d_c1;
    a = (a > 0.f) ? a : 0.2f * a;
    float ex = __expf(a);
    float* ag = d_agg1 + (size_t)d * 16;
    red4(ag + 0,  ex * v0.x, ex * v0.y, ex * v0.z, ex * v0.w);
    red4(ag + 4,  ex * v1.x, ex * v1.y, ex * v1.z, ex * v1.w);
    red4(ag + 8,  ex * v2.x, ex * v2.y, ex * v2.z, ex * v2.w);
    red4(ag + 12, ex * v3.x, ex * v3.y, ex * v3.z, ex);      // .w accumulates denom
}

// ---------------- post layer 1: normalize + bias, BN stats ----------------
__global__ void __launch_bounds__(256) k_post1(const float* __restrict__ b1, int n_nodes) {
    int n = blockIdx.x * 256 + threadIdx.x;
    float h[15];
#pragma unroll
    for (int o = 0; o < 15; ++o) h[o] = 0.f;
    if (n < n_nodes) {
        float inv = 1.f / (d_agg1[n * 16 + 15] + 1e-16f);
#pragma unroll
        for (int o = 0; o < 15; ++o) {
            h[o] = d_agg1[n * 16 + o] * inv + b1[o];
            d_h1[n * 16 + o] = h[o];
        }
    }
    __shared__ float ssum[15], ssq[15];
    if (threadIdx.x < 15) { ssum[threadIdx.x] = 0.f; ssq[threadIdx.x] = 0.f; }
    __syncthreads();
#pragma unroll
    for (int o = 0; o < 15; ++o) {
        float s = h[o], s2 = h[o] * h[o];
        for (int off = 16; off; off >>= 1) {
            s  += __shfl_down_sync(0xffffffffu, s, off);
            s2 += __shfl_down_sync(0xffffffffu, s2, off);
        }
        if ((threadIdx.x & 31) == 0) { atomicAdd(&ssum[o], s); atomicAdd(&ssq[o], s2); }
    }
    __syncthreads();
    if (threadIdx.x < 15)                               atomicAdd(&d_stats[threadIdx.x], ssum[threadIdx.x]);
    else if (threadIdx.x >= 16 && threadIdx.x < 31)     atomicAdd(&d_stats[threadIdx.x], ssq[threadIdx.x - 16]);
}

__global__ void k_bnfin1(const float* __restrict__ g, const float* __restrict__ beta, int n_nodes) {
    int o = threadIdx.x;
    if (o < 15) {
        float invn = 1.f / (float)n_nodes;
        float mean = d_stats[o] * invn;
        float var  = d_stats[16 + o] * invn - mean * mean;
        float sc = g[o] * rsqrtf(var + 1e-5f);
        d_bn1s[o] = sc;
        d_bn1b[o] = beta[o] - mean * sc;
    }
}

// ---------------- layer-2: BN+ELU then [N,15] @ [15,48] ----------------
__global__ void __launch_bounds__(256) k_gemm2(int n_nodes) {
    __shared__ float w2s[720];
    for (int i = threadIdx.x; i < 720; i += 256) w2s[i] = d_CW2[i];
    __syncthreads();
    int n = blockIdx.x * 256 + threadIdx.x;
    if (n >= n_nodes) return;
    float x2[15];
#pragma unroll
    for (int o = 0; o < 15; ++o) {
        float v = d_h1[n * 16 + o] * d_bn1s[o] + d_bn1b[o];
        x2[o] = (v > 0.f) ? v : expm1f(v);
    }
    float outv[48];
#pragma unroll
    for (int c = 0; c < 48; ++c) {
        float s = 0.f;
#pragma unroll
        for (int i = 0; i < 15; ++i) s += x2[i] * w2s[i * 48 + c];
        outv[c] = s;
    }
#pragma unroll
    for (int c = 0; c < 40; ++c) d_xt2[n * 64 + (c / 10) * 16 + (c % 10)] = outv[c];
#pragma unroll
    for (int r = 0; r < 4; ++r) {
        d_aq2[n * 4 + r] = outv[40 + r];
        d_xt2[n * 64 + r * 16 + 10] = outv[44 + r];   // ak2 packed
        d_xt2[n * 64 + r * 16 + 11] = 0.f;
    }
}

// ---------------- edge pass 2 ----------------
__global__ void __launch_bounds__(256) k_edge2(const int* __restrict__ ei, const int* __restrict__ et,
                                               const float* __restrict__ ea, int ne) {
    int e = blockIdx.x * 256 + threadIdx.x;
    if (e >= ne) return;
    int s = ei[e], d = ei[ne + e];
    int r = et[e];
    const float4* xp = reinterpret_cast<const float4*>(d_xt2 + ((size_t)s * 4 + r) * 16);
    float4 v0 = xp[0], v1 = xp[1], v2 = xp[2];   // v2.z = ak2[s,r]
    float a = d_aq2[d * 4 + r] + v2.z + ea[e] * d_c2;
    a = (a > 0.f) ? a : 0.2f * a;
    float ex = __expf(a);
    float* ag = d_agg2 + (size_t)d * 12;
    red4(ag + 0, ex * v0.x, ex * v0.y, ex * v0.z, ex * v0.w);
    red4(ag + 4, ex * v1.x, ex * v1.y, ex * v1.z, ex * v1.w);
    red4(ag + 8, ex * v2.x, ex * v2.y, ex, 0.f);             // slot10 = denom
}

// ---------------- post layer 2 ----------------
__global__ void __launch_bounds__(256) k_post2(const float* __restrict__ b2, int n_nodes) {
    int n = blockIdx.x * 256 + threadIdx.x;
    float h[10];
#pragma unroll
    for (int o = 0; o < 10; ++o) h[o] = 0.f;
    if (n < n_nodes) {
        float inv = 1.f / (d_agg2[n * 12 + 10] + 1e-16f);
#pragma unroll
        for (int o = 0; o < 10; ++o) {
            h[o] = d_agg2[n * 12 + o] * inv + b2[o];
            d_h2[n * 10 + o] = h[o];
        }
    }
    __shared__ float ssum[10], ssq[10];
    if (threadIdx.x < 10) { ssum[threadIdx.x] = 0.f; ssq[threadIdx.x] = 0.f; }
    __syncthreads();
#pragma unroll
    for (int o = 0; o < 10; ++o) {
        float s = h[o], s2 = h[o] * h[o];
        for (int off = 16; off; off >>= 1) {
            s  += __shfl_down_sync(0xffffffffu, s, off);
            s2 += __shfl_down_sync(0xffffffffu, s2, off);
        }
        if ((threadIdx.x & 31) == 0) { atomicAdd(&ssum[o], s); atomicAdd(&ssq[o], s2); }
    }
    __syncthreads();
    if (threadIdx.x < 10)                               atomicAdd(&d_stats[32 + threadIdx.x], ssum[threadIdx.x]);
    else if (threadIdx.x >= 16 && threadIdx.x < 26)     atomicAdd(&d_stats[48 + threadIdx.x - 16], ssq[threadIdx.x - 16]);
}

__global__ void k_bnfin2(const float* __restrict__ g, const float* __restrict__ beta, int n_nodes) {
    int o = threadIdx.x;
    if (o < 10) {
        float invn = 1.f / (float)n_nodes;
        float mean = d_stats[32 + o] * invn;
        float var  = d_stats[48 + o] * invn - mean * mean;
        float sc = g[o] * rsqrtf(var + 1e-5f);
        d_bn2s[o] = sc;
        d_bn2b[o] = beta[o] - mean * sc;
    }
}

// ---------------- head ----------------
__global__ void __launch_bounds__(256) k_head(const float* __restrict__ wh, const float* __restrict__ bh,
                                              float* __restrict__ out, int n_nodes) {
    int n = blockIdx.x * 256 + threadIdx.x;
    if (n >= n_nodes) return;
    float s = bh[0];
#pragma unroll
    for (int o = 0; o < 10; ++o) {
        float v = d_h2[n * 10 + o] * d_bn2s[o] + d_bn2b[o];
        v = (v > 0.f) ? v : expm1f(v);
        s += v * wh[o];
    }
    out[n] = s;
}

// ---------------- launch ----------------
extern "C" void kernel_launch(void* const* d_in, const int* in_sizes, int n_in,
                              void* d_out, int out_size) {
    const float* x   = (const float*)d_in[0];
    const int*   ei  = (const int*)  d_in[1];
    const int*   et  = (const int*)  d_in[2];
    const float* ea  = (const float*)d_in[3];
    const float* W1  = (const float*)d_in[4];
    const float* q1  = (const float*)d_in[5];
    const float* k1  = (const float*)d_in[6];
    const float* e1  = (const float*)d_in[7];
    const float* We1 = (const float*)d_in[8];
    const float* b1  = (const float*)d_in[9];
    const float* W2  = (const float*)d_in[10];
    const float* q2  = (const float*)d_in[11];
    const float* k2  = (const float*)d_in[12];
    const float* e2  = (const float*)d_in[13];
    const float* We2 = (const float*)d_in[14];
    const float* b2  = (const float*)d_in[15];
    const float* g1  = (const float*)d_in[16];
    const float* bt1 = (const float*)d_in[17];
    const float* g2  = (const float*)d_in[18];
    const float* bt2 = (const float*)d_in[19];
    const float* wh  = (const float*)d_in[20];
    const float* bh  = (const float*)d_in[21];
    float* out = (float*)d_out;

    int n  = in_sizes[0] / FF;
    int ne = in_sizes[1] / 2;

    k_zero<<<2048, 256>>>();
    k_build1<<<(128 * 68 + 255) / 256, 256>>>(W1, q1, k1);
    k_build2<<<3, 256>>>(W2, q2, k2, We1, e1, We2, e2);
    k_gemm1<<<(n + 63) / 64, 256>>>(x, n);
    k_edge1<<<(ne + 255) / 256, 256>>>(ei, et, ea, ne);
    k_post1<<<(n + 255) / 256, 256>>>(b1, n);
    k_bnfin1<<<1, 32>>>(g1, bt1, n);
    k_gemm2<<<(n + 255) / 256, 256>>>(n);
    k_edge2<<<(ne + 255) / 256, 256>>>(ei, et, ea, ne);
    k_post2<<<(n + 255) / 256, 256>>>(b2, n);
    k_bnfin2<<<1, 32>>>(g2, bt2, n);
    k_head<<<(n + 255) / 256, 256>>>(wh, bh, out, n);
}

// round 8
// speedup vs baseline: 1.4033x; 1.0016x over previous
#include <cuda_runtime.h>
#include <math.h>

#define NN 50000
#define FF 128

// ---------------- scratch (device globals; no allocation) ----------------
__device__ __align__(16) float d_xt1[NN * 64];   // [N][4][16], slot15 = ak1
__device__ float d_aq1[NN * 4];
__device__ __align__(16) float d_agg1[NN * 16];  // slot15 = denom
__device__ float d_h1[NN * 16];
__device__ __align__(16) float d_xt2[NN * 64];   // [N][4][16], slot10 = ak2
__device__ float d_aq2[NN * 4];
__device__ __align__(16) float d_agg2[NN * 12];  // slot10 = denom
__device__ float d_h2[NN * 10];
// padded weight layout: [ft][f][cg][20], col = cg*17 + c (c<17), zeros pad
__device__ __align__(16) float d_CW1p[4 * 32 * 80];
__device__ float d_CW2[15 * 48];    // cols 0..39 = W2, 40..43 = W2@q2, 44..47 = W2@k2
__device__ float d_stats[64];
__device__ float d_bn1s[15], d_bn1b[15], d_bn2s[10], d_bn2b[10];
__device__ float d_c1, d_c2;

// ---------------- helpers ----------------
__device__ __forceinline__ void red4(float* p, float a, float b, float c, float d) {
    asm volatile("red.global.add.v4.f32 [%0], {%1,%2,%3,%4};"
                 :: "l"(p), "f"(a), "f"(b), "f"(c), "f"(d) : "memory");
}

// ---------------- init ----------------
__global__ void k_zero() {
    const int tot = NN * 16 + NN * 12 + 64;
    for (int i = blockIdx.x * blockDim.x + threadIdx.x; i < tot; i += gridDim.x * blockDim.x) {
        if (i < NN * 16)            d_agg1[i] = 0.f;
        else if (i < NN * 28)       d_agg2[i - NN * 16] = 0.f;
        else                        d_stats[i - NN * 28] = 0.f;
    }
}

// ---------------- weight prep (padded layout) ----------------
__global__ void k_build1(const float* __restrict__ W1, const float* __restrict__ q1,
                         const float* __restrict__ k1) {
    int i = blockIdx.x * 256 + threadIdx.x;
    if (i >= 4 * 32 * 80) return;
    int c20 = i % 20, cg = (i / 20) & 3, f = (i / 80) & 31, ft = i / 2560;
    int fg = ft * 32 + f;
    float v = 0.f;
    if (c20 < 17) {
        int col = cg * 17 + c20;
        if (col < 60) {
            int r = col / 15, o = col % 15;
            v = W1[(r * 128 + fg) * 15 + o];
        } else if (col < 64) {
            int r = col - 60; float s = 0.f;
            for (int o = 0; o < 15; ++o) s += W1[(r * 128 + fg) * 15 + o] * q1[o];
            v = s;
        } else {
            int r = col - 64; float s = 0.f;
            for (int o = 0; o < 15; ++o) s += W1[(r * 128 + fg) * 15 + o] * k1[o];
            v = s;
        }
    }
    d_CW1p[i] = v;
}

__global__ void k_build2(const float* __restrict__ W2, const float* __restrict__ q2,
                         const float* __restrict__ k2,
                         const float* __restrict__ We1, const float* __restrict__ e1,
                         const float* __restrict__ We2, const float* __restrict__ e2) {
    int i = blockIdx.x * 256 + threadIdx.x;
    if (i == 0) {
        float s = 0.f;
        for (int o = 0; o < 15; ++o) s += We1[o] * e1[o];
        d_c1 = s;
        float t = 0.f;
        for (int o = 0; o < 10; ++o) t += We2[o] * e2[o];
        d_c2 = t;
    }
    if (i >= 15 * 48) return;
    int f = i / 48, c = i % 48;
    float v;
    if (c < 40) {
        int r = c / 10, o = c % 10;
        v = W2[(r * 15 + f) * 10 + o];
    } else if (c < 44) {
        int r = c - 40; float s = 0.f;
        for (int o = 0; o < 10; ++o) s += W2[(r * 15 + f) * 10 + o] * q2[o];
        v = s;
    } else {
        int r = c - 44; float s = 0.f;
        for (int o = 0; o < 10; ++o) s += W2[(r * 15 + f) * 10 + o] * k2[o];
        v = s;
    }
    d_CW2[i] = v;
}

// ---------------- layer-1 GEMM: [N,128] @ [128,68], vectorized LDS ----------------
// 256 threads = 64 nodes x 4 col-groups; thread owns 1 node x 17 cols.
__global__ void __launch_bounds__(256) k_gemm1(const float* __restrict__ x, int n_nodes) {
    __shared__ __align__(16) float xs[64 * 36];   // 64 nodes x 32 f, stride 36 (16B aligned)
    __shared__ __align__(16) float ws[32 * 80];   // [f][cg*20 + c]
    const int tid = threadIdx.x;
    const int nbase = blockIdx.x * 64;
    const int ng = tid >> 2, cg = tid & 3;

    float acc[17];
#pragma unroll
    for (int c = 0; c < 17; ++c) acc[c] = 0.f;

    const bool full = (nbase + 64 <= n_nodes);

    for (int ft = 0; ft < 4; ++ft) {
        // x tile: 64 nodes x 32 f = 512 float4; 2 per thread
#pragma unroll
        for (int k = 0; k < 2; ++k) {
            int idx = k * 256 + tid;
            int nl = idx >> 3, q = idx & 7;
            int n = nbase + nl;
            float4 v = make_float4(0.f, 0.f, 0.f, 0.f);
            if (full || n < n_nodes)
                v = *reinterpret_cast<const float4*>(x + (size_t)n * FF + ft * 32 + q * 4);
            *reinterpret_cast<float4*>(&xs[nl * 36 + q * 4]) = v;
        }
        // ws tile: 2560 floats = 640 float4
        {
            const float4* src = reinterpret_cast<const float4*>(d_CW1p + ft * 2560);
            float4* dst = reinterpret_cast<float4*>(ws);
            for (int i = tid; i < 640; i += 256) dst[i] = src[i];
        }
        __syncthreads();

#pragma unroll
        for (int f4 = 0; f4 < 32; f4 += 4) {
            float4 xv = *reinterpret_cast<const float4*>(&xs[ng * 36 + f4]);
#pragma unroll
            for (int j = 0; j < 4; ++j) {
                float xj = (j == 0) ? xv.x : (j == 1) ? xv.y : (j == 2) ? xv.z : xv.w;
                const float* wr = &ws[(f4 + j) * 80 + cg * 20];
                float4 w0 = *reinterpret_cast<const float4*>(wr + 0);
                float4 w1 = *reinterpret_cast<const float4*>(wr + 4);
                float4 w2 = *reinterpret_cast<const float4*>(wr + 8);
                float4 w3 = *reinterpret_cast<const float4*>(wr + 12);
                float w16 = wr[16];
                acc[0]  += xj * w0.x;  acc[1]  += xj * w0.y;
                acc[2]  += xj * w0.z;  acc[3]  += xj * w0.w;
                acc[4]  += xj * w1.x;  acc[5]  += xj * w1.y;
                acc[6]  += xj * w1.z;  acc[7]  += xj * w1.w;
                acc[8]  += xj * w2.x;  acc[9]  += xj * w2.y;
                acc[10] += xj * w2.z;  acc[11] += xj * w2.w;
                acc[12] += xj * w3.x;  acc[13] += xj * w3.y;
                acc[14] += xj * w3.z;  acc[15] += xj * w3.w;
                acc[16] += xj * w16;
            }
        }
        __syncthreads();
    }

    int n = nbase + ng;
    if (n < n_nodes) {
#pragma unroll
        for (int c = 0; c < 17; ++c) {
            int col = cg * 17 + c;
            float v = acc[c];
            if (col < 60)      d_xt1[n * 64 + (col / 15) * 16 + (col % 15)] = v;
            else if (col < 64) d_aq1[n * 4 + col - 60] = v;
            else               d_xt1[n * 64 + (col - 64) * 16 + 15] = v;   // ak packed
        }
    }
}

// ---------------- edge pass 1 ----------------
__global__ void __launch_bounds__(256) k_edge1(const int* __restrict__ ei, const int* __restrict__ et,
                                               const float* __restrict__ ea, int ne) {
    int e = blockIdx.x * 256 + threadIdx.x;
    if (e >= ne) return;
    int s = ei[e], d = ei[ne + e];
    int r = et[e];
    const float4* xp = reinterpret_cast<const float4*>(d_xt1 + ((size_t)s * 4 + r) * 16);
    float4 v0 = xp[0], v1 = xp[1], v2 = xp[2], v3 = xp[3];   // v3.w = ak[s,r]
    float a = d_aq1[d * 4 + r] + v3.w + ea[e] * d_c1;
    a = (a > 0.f) ? a : 0.2f * a;
    float ex = __expf(a);
    float* ag = d_agg1 + (size_t)d * 16;
    red4(ag + 0,  ex * v0.x, ex * v0.y, ex * v0.z, ex * v0.w);
    red4(ag + 4,  ex * v1.x, ex * v1.y, ex * v1.z, ex * v1.w);
    red4(ag + 8,  ex * v2.x, ex * v2.y, ex * v2.z, ex * v2.w);
    red4(ag + 12, ex * v3.x, ex * v3.y, ex * v3.z, ex);      // .w accumulates denom
}

// ---------------- post layer 1 ----------------
__global__ void __launch_bounds__(256) k_post1(const float* __restrict__ b1, int n_nodes) {
    int n = blockIdx.x * 256 + threadIdx.x;
    float h[15];
#pragma unroll
    for (int o = 0; o < 15; ++o) h[o] = 0.f;
    if (n < n_nodes) {
        float inv = 1.f / (d_agg1[n * 16 + 15] + 1e-16f);
#pragma unroll
        for (int o = 0; o < 15; ++o) {
            h[o] = d_agg1[n * 16 + o] * inv + b1[o];
            d_h1[n * 16 + o] = h[o];
        }
    }
    __shared__ float ssum[15], ssq[15];
    if (threadIdx.x < 15) { ssum[threadIdx.x] = 0.f; ssq[threadIdx.x] = 0.f; }
    __syncthreads();
#pragma unroll
    for (int o = 0; o < 15; ++o) {
        float s = h[o], s2 = h[o] * h[o];
        for (int off = 16; off; off >>= 1) {
            s  += __shfl_down_sync(0xffffffffu, s, off);
            s2 += __shfl_down_sync(0xffffffffu, s2, off);
        }
        if ((threadIdx.x & 31) == 0) { atomicAdd(&ssum[o], s); atomicAdd(&ssq[o], s2); }
    }
    __syncthreads();
    if (threadIdx.x < 15)                               atomicAdd(&d_stats[threadIdx.x], ssum[threadIdx.x]);
    else if (threadIdx.x >= 16 && threadIdx.x < 31)     atomicAdd(&d_stats[threadIdx.x], ssq[threadIdx.x - 16]);
}

__global__ void k_bnfin1(const float* __restrict__ g, const float* __restrict__ beta, int n_nodes) {
    int o = threadIdx.x;
    if (o < 15) {
        float invn = 1.f / (float)n_nodes;
        float mean = d_stats[o] * invn;
        float var  = d_stats[16 + o] * invn - mean * mean;
        float sc = g[o] * rsqrtf(var + 1e-5f);
        d_bn1s[o] = sc;
        d_bn1b[o] = beta[o] - mean * sc;
    }
}

// ---------------- layer-2: BN+ELU then [N,15] @ [15,48] ----------------
__global__ void __launch_bounds__(256) k_gemm2(int n_nodes) {
    __shared__ float w2s[720];
    for (int i = threadIdx.x; i < 720; i += 256) w2s[i] = d_CW2[i];
    __syncthreads();
    int n = blockIdx.x * 256 + threadIdx.x;
    if (n >= n_nodes) return;
    float x2[15];
#pragma unroll
    for (int o = 0; o < 15; ++o) {
        float v = d_h1[n * 16 + o] * d_bn1s[o] + d_bn1b[o];
        x2[o] = (v > 0.f) ? v : expm1f(v);
    }
    float outv[48];
#pragma unroll
    for (int c = 0; c < 48; ++c) {
        float s = 0.f;
#pragma unroll
        for (int i = 0; i < 15; ++i) s += x2[i] * w2s[i * 48 + c];
        outv[c] = s;
    }
#pragma unroll
    for (int c = 0; c < 40; ++c) d_xt2[n * 64 + (c / 10) * 16 + (c % 10)] = outv[c];
#pragma unroll
    for (int r = 0; r < 4; ++r) {
        d_aq2[n * 4 + r] = outv[40 + r];
        d_xt2[n * 64 + r * 16 + 10] = outv[44 + r];   // ak2 packed
        d_xt2[n * 64 + r * 16 + 11] = 0.f;
    }
}

// ---------------- edge pass 2 ----------------
__global__ void __launch_bounds__(256) k_edge2(const int* __restrict__ ei, const int* __restrict__ et,
                                               const float* __restrict__ ea, int ne) {
    int e = blockIdx.x * 256 + threadIdx.x;
    if (e >= ne) return;
    int s = ei[e], d = ei[ne + e];
    int r = et[e];
    const float4* xp = reinterpret_cast<const float4*>(d_xt2 + ((size_t)s * 4 + r) * 16);
    float4 v0 = xp[0], v1 = xp[1], v2 = xp[2];   // v2.z = ak2[s,r]
    float a = d_aq2[d * 4 + r] + v2.z + ea[e] * d_c2;
    a = (a > 0.f) ? a : 0.2f * a;
    float ex = __expf(a);
    float* ag = d_agg2 + (size_t)d * 12;
    red4(ag + 0, ex * v0.x, ex * v0.y, ex * v0.z, ex * v0.w);
    red4(ag + 4, ex * v1.x, ex * v1.y, ex * v1.z, ex * v1.w);
    red4(ag + 8, ex * v2.x, ex * v2.y, ex, 0.f);             // slot10 = denom
}

// ---------------- post layer 2 ----------------
__global__ void __launch_bounds__(256) k_post2(const float* __restrict__ b2, int n_nodes) {
    int n = blockIdx.x * 256 + threadIdx.x;
    float h[10];
#pragma unroll
    for (int o = 0; o < 10; ++o) h[o] = 0.f;
    if (n < n_nodes) {
        float inv = 1.f / (d_agg2[n * 12 + 10] + 1e-16f);
#pragma unroll
        for (int o = 0; o < 10; ++o) {
            h[o] = d_agg2[n * 12 + o] * inv + b2[o];
            d_h2[n * 10 + o] = h[o];
        }
    }
    __shared__ float ssum[10], ssq[10];
    if (threadIdx.x < 10) { ssum[threadIdx.x] = 0.f; ssq[threadIdx.x] = 0.f; }
    __syncthreads();
#pragma unroll
    for (int o = 0; o < 10; ++o) {
        float s = h[o], s2 = h[o] * h[o];
        for (int off = 16; off; off >>= 1) {
            s  += __shfl_down_sync(0xffffffffu, s, off);
            s2 += __shfl_down_sync(0xffffffffu, s2, off);
        }
        if ((threadIdx.x & 31) == 0) { atomicAdd(&ssum[o], s); atomicAdd(&ssq[o], s2); }
    }
    __syncthreads();
    if (threadIdx.x < 10)                               atomicAdd(&d_stats[32 + threadIdx.x], ssum[threadIdx.x]);
    else if (threadIdx.x >= 16 && threadIdx.x < 26)     atomicAdd(&d_stats[48 + threadIdx.x - 16], ssq[threadIdx.x - 16]);
}

__global__ void k_bnfin2(const float* __restrict__ g, const float* __restrict__ beta, int n_nodes) {
    int o = threadIdx.x;
    if (o < 10) {
        float invn = 1.f / (float)n_nodes;
        float mean = d_stats[32 + o] * invn;
        float var  = d_stats[48 + o] * invn - mean * mean;
        float sc = g[o] * rsqrtf(var + 1e-5f);
        d_bn2s[o] = sc;
        d_bn2b[o] = beta[o] - mean * sc;
    }
}

// ---------------- head ----------------
__global__ void __launch_bounds__(256) k_head(const float* __restrict__ wh, const float* __restrict__ bh,
                                              float* __restrict__ out, int n_nodes) {
    int n = blockIdx.x * 256 + threadIdx.x;
    if (n >= n_nodes) return;
    float s = bh[0];
#pragma unroll
    for (int o = 0; o < 10; ++o) {
        float v = d_h2[n * 10 + o] * d_bn2s[o] + d_bn2b[o];
        v = (v > 0.f) ? v : expm1f(v);
        s += v * wh[o];
    }
    out[n] = s;
}

// ---------------- launch ----------------
extern "C" void kernel_launch(void* const* d_in, const int* in_sizes, int n_in,
                              void* d_out, int out_size) {
    const float* x   = (const float*)d_in[0];
    const int*   ei  = (const int*)  d_in[1];
    const int*   et  = (const int*)  d_in[2];
    const float* ea  = (const float*)d_in[3];
    const float* W1  = (const float*)d_in[4];
    const float* q1  = (const float*)d_in[5];
    const float* k1  = (const float*)d_in[6];
    const float* e1  = (const float*)d_in[7];
    const float* We1 = (const float*)d_in[8];
    const float* b1  = (const float*)d_in[9];
    const float* W2  = (const float*)d_in[10];
    const float* q2  = (const float*)d_in[11];
    const float* k2  = (const float*)d_in[12];
    const float* e2  = (const float*)d_in[13];
    const float* We2 = (const float*)d_in[14];
    const float* b2  = (const float*)d_in[15];
    const float* g1  = (const float*)d_in[16];
    const float* bt1 = (const float*)d_in[17];
    const float* g2  = (const float*)d_in[18];
    const float* bt2 = (const float*)d_in[19];
    const float* wh  = (const float*)d_in[20];
    const float* bh  = (const float*)d_in[21];
    float* out = (float*)d_out;

    int n  = in_sizes[0] / FF;
    int ne = in_sizes[1] / 2;

    k_zero<<<2048, 256>>>();
    k_build1<<<(4 * 32 * 80 + 255) / 256, 256>>>(W1, q1, k1);
    k_build2<<<3, 256>>>(W2, q2, k2, We1, e1, We2, e2);
    k_gemm1<<<(n + 63) / 64, 256>>>(x, n);
    k_edge1<<<(ne + 255) / 256, 256>>>(ei, et, ea, ne);
    k_post1<<<(n + 255) / 256, 256>>>(b1, n);
    k_bnfin1<<<1, 32>>>(g1, bt1, n);
    k_gemm2<<<(n + 255) / 256, 256>>>(n);
    k_edge2<<<(ne + 255) / 256, 256>>>(ei, et, ea, ne);
    k_post2<<<(n + 255) / 256, 256>>>(b2, n);
    k_bnfin2<<<1, 32>>>(g2, bt2, n);
    k_head<<<(n + 255) / 256, 256>>>(wh, bh, out, n);
}